// round 11
// baseline (speedup 1.0000x reference)
#include <cuda_runtime.h>
#include <cuda_bf16.h>
#include <cstdint>

#define S_LEN 2048
#define D_DIM 2048
#define NH 32
#define NB 8
#define HB 256    // NH*NB
#define NBIG 2816 // 768 (qkv) + 2048 (gate)

// -------- scratch (no allocations allowed) --------
__device__ float g_pq[NH * S_LEN * NB];   // [h][s][bit], pre-scaled by 2
__device__ float g_pk[NH * S_LEN * NB];
__device__ float g_pv[NH * S_LEN * NB];
__device__ float g_sumk[NH * S_LEN];
__device__ float g_op[S_LEN * HB];        // (e1-e0)*attn_out
__device__ float g_bias[D_DIM];           // e0 @ Wo

__device__ __nv_bfloat16 g_hsH[S_LEN * D_DIM];
__device__ __nv_bfloat16 g_hsL[S_LEN * D_DIM];
__device__ __nv_bfloat16 g_WbigH[NBIG * D_DIM];  // rows: 0-255 q,256-511 k,512-767 v,768+ gate
__device__ __nv_bfloat16 g_WbigL[NBIG * D_DIM];

__device__ __forceinline__ float fsigmoid(float x) {
    return 1.0f / (1.0f + __expf(-x));
}

__device__ __forceinline__ uint32_t smem_u32(const void* p) {
    uint32_t a;
    asm("{ .reg .u64 t; cvta.to.shared.u64 t, %1; cvt.u32.u64 %0, t; }" : "=r"(a) : "l"(p));
    return a;
}
__device__ __forceinline__ void cp16(uint32_t dst, const void* src) {
    asm volatile("cp.async.cg.shared.global [%0], [%1], 16;" :: "r"(dst), "l"(src));
}
__device__ __forceinline__ void cp_commit() {
    asm volatile("cp.async.commit_group;" ::: "memory");
}
template <int N> __device__ __forceinline__ void cp_wait() {
    asm volatile("cp.async.wait_group %0;" :: "n"(N) : "memory");
}
__device__ __forceinline__ uint32_t lds32(uint32_t a) {
    uint32_t v;
    asm volatile("ld.shared.b32 %0, [%1];" : "=r"(v) : "r"(a));
    return v;
}
__device__ __forceinline__ void mma16816(float* d, const uint32_t* a, uint32_t b0, uint32_t b1) {
    asm volatile(
        "mma.sync.aligned.m16n8k16.row.col.f32.bf16.bf16.f32 "
        "{%0,%1,%2,%3}, {%4,%5,%6,%7}, {%8,%9}, {%0,%1,%2,%3};"
        : "+f"(d[0]), "+f"(d[1]), "+f"(d[2]), "+f"(d[3])
        : "r"(a[0]), "r"(a[1]), "r"(a[2]), "r"(a[3]), "r"(b0), "r"(b1));
}

// ---------------- packing kernels ----------------
__global__ void pack_hilo(const float* __restrict__ src, __nv_bfloat16* __restrict__ h,
                          __nv_bfloat16* __restrict__ l, int n4) {
    int i = blockIdx.x * blockDim.x + threadIdx.x;
    if (i >= n4) return;
    float4 v = ((const float4*)src)[i];
    __nv_bfloat16 h0 = __float2bfloat16(v.x), h1 = __float2bfloat16(v.y);
    __nv_bfloat16 h2 = __float2bfloat16(v.z), h3 = __float2bfloat16(v.w);
    __nv_bfloat16 l0 = __float2bfloat16(v.x - __bfloat162float(h0));
    __nv_bfloat16 l1 = __float2bfloat16(v.y - __bfloat162float(h1));
    __nv_bfloat16 l2 = __float2bfloat16(v.z - __bfloat162float(h2));
    __nv_bfloat16 l3 = __float2bfloat16(v.w - __bfloat162float(h3));
    ((__nv_bfloat162*)h)[i * 2]     = __nv_bfloat162(h0, h1);
    ((__nv_bfloat162*)h)[i * 2 + 1] = __nv_bfloat162(h2, h3);
    ((__nv_bfloat162*)l)[i * 2]     = __nv_bfloat162(l0, l1);
    ((__nv_bfloat162*)l)[i * 2 + 1] = __nv_bfloat162(l2, l3);
}

// dst[rowoff+n][k] = src[k][n] split hi/lo. src: [K x N] row-major.
__global__ void pack_T(const float* __restrict__ src, __nv_bfloat16* __restrict__ dh,
                       __nv_bfloat16* __restrict__ dl, int K, int N, int rowoff, int dstride) {
    __shared__ float t[32][33];
    int k0 = blockIdx.y * 32, n0 = blockIdx.x * 32;
    int tx = threadIdx.x, ty = threadIdx.y;
#pragma unroll
    for (int i = 0; i < 32; i += 8)
        t[ty + i][tx] = src[(size_t)(k0 + ty + i) * N + n0 + tx];
    __syncthreads();
#pragma unroll
    for (int i = 0; i < 32; i += 8) {
        float v = t[tx][ty + i];
        size_t o = (size_t)(rowoff + n0 + ty + i) * dstride + k0 + tx;
        __nv_bfloat16 h = __float2bfloat16(v);
        dh[o] = h;
        dl[o] = __float2bfloat16(v - __bfloat162float(h));
    }
}

// ---------------- fused qkv+gate mma GEMM ----------------
// C[M, NBIG] = A x B^T. A=[M,K] bf16 hi/lo, B=[NBIG,K] bf16 hi/lo.
// K extended 3x: seg0 Ah*Bh, seg1 Al*Bh, seg2 Ah*Bl.
// CTA 128x128, BK=32, padded rows (80B), direct ld.shared frags, 2-stage cp.async.
#define BM 128
#define BN 128
#define BK 32
#define ROWB 80
#define A_BYTES (128 * ROWB)         // 10240
#define STAGE_BYTES (2 * A_BYTES)    // 20480
#define GEMM_SMEM (2 * STAGE_BYTES)  // 40960 (< 48KB, no opt-in)
#define SEGCH (D_DIM / BK)           // 64
#define NCH (3 * SEGCH)              // 192

__device__ __forceinline__ void load_tile(
    const __nv_bfloat16* __restrict__ ap, const __nv_bfloat16* __restrict__ bp,
    uint32_t sa, uint32_t sb, uint32_t soff)
{
    cp16(sa + soff, ap);
    cp16(sa + soff + 64 * ROWB, ap + (size_t)64 * D_DIM);
    cp16(sb + soff, bp);
    cp16(sb + soff + 64 * ROWB, bp + (size_t)64 * D_DIM);
}

__device__ __forceinline__ void compute_tile(
    uint32_t sa, uint32_t sb, uint32_t a_base, uint32_t b_base, float (&acc)[4][4][4])
{
#pragma unroll
    for (int ks = 0; ks < 2; ++ks) {
        uint32_t b0[4], b1[4];
#pragma unroll
        for (int ni = 0; ni < 4; ++ni) {
            uint32_t ba = sb + b_base + ni * 8 * ROWB + ks * 32;
            b0[ni] = lds32(ba);
            b1[ni] = lds32(ba + 16);
        }
#pragma unroll
        for (int mi = 0; mi < 4; ++mi) {
            uint32_t aa = sa + a_base + mi * 16 * ROWB + ks * 32;
            uint32_t a[4];
            a[0] = lds32(aa);
            a[1] = lds32(aa + 8 * ROWB);
            a[2] = lds32(aa + 16);
            a[3] = lds32(aa + 8 * ROWB + 16);
#pragma unroll
            for (int ni = 0; ni < 4; ++ni)
                mma16816(acc[mi][ni], a, b0[ni], b1[ni]);
        }
    }
}

__global__ void __launch_bounds__(256) fused_qkvgate(
    const __nv_bfloat16* __restrict__ Ah, const __nv_bfloat16* __restrict__ Al,
    const __nv_bfloat16* __restrict__ Bh, const __nv_bfloat16* __restrict__ Bl,
    float* __restrict__ out)
{
    extern __shared__ char smem[];
    const uint32_t sbase = smem_u32(smem);
    const int tid = threadIdx.x;
    const int lane = tid & 31, wid = tid >> 5;
    const int wm = wid & 1, wn = wid >> 1;    // warp tile 64m x 32n
    const int tq = lane >> 2, tr = lane & 3;

    const size_t arow0 = (size_t)blockIdx.y * BM;
    const size_t brow0 = (size_t)blockIdx.x * BN;
    const int r0 = tid >> 2, c16 = tid & 3;
    const uint32_t soff = (uint32_t)(r0 * ROWB + c16 * 16);

    float acc[4][4][4];
#pragma unroll
    for (int mi = 0; mi < 4; ++mi)
#pragma unroll
        for (int ni = 0; ni < 4; ++ni)
#pragma unroll
            for (int j = 0; j < 4; ++j) acc[mi][ni][j] = 0.0f;

    const uint32_t a_base = (uint32_t)((wm * 64 + tq) * ROWB + tr * 4);
    const uint32_t b_base = (uint32_t)((wn * 32 + tq) * ROWB + tr * 4);

    // prologue: chunk 0 (seg 0, koff 0)
    load_tile(Ah + (arow0 + r0) * D_DIM + c16 * 8,
              Bh + (brow0 + r0) * D_DIM + c16 * 8,
              sbase, sbase + A_BYTES, soff);
    cp_commit();

    for (int c = 0; c < NCH; ++c) {
        const int cn = c + 1;
        if (cn < NCH) {
            const int seg = cn / SEGCH;
            const int koff = (cn - seg * SEGCH) * BK;
            const __nv_bfloat16* As = (seg == 1) ? Al : Ah;
            const __nv_bfloat16* Bs = (seg == 2) ? Bl : Bh;
            const uint32_t s = sbase + (cn & 1) * STAGE_BYTES;
            load_tile(As + (arow0 + r0) * D_DIM + koff + c16 * 8,
                      Bs + (brow0 + r0) * D_DIM + koff + c16 * 8,
                      s, s + A_BYTES, soff);
        }
        cp_commit();
        cp_wait<1>();
        __syncthreads();
        const uint32_t s = sbase + (c & 1) * STAGE_BYTES;
        compute_tile(s, s + A_BYTES, a_base, b_base, acc);
        __syncthreads();
    }

    // epilogue: c0,c1 -> [tq][2tr,2tr+1]; c2,c3 -> [tq+8][2tr,2tr+1]
    const int rA = blockIdx.y * BM + wm * 64 + tq;
    const int cA = blockIdx.x * BN + wn * 32 + tr * 2;
#pragma unroll
    for (int mi = 0; mi < 4; ++mi) {
#pragma unroll
        for (int ni = 0; ni < 4; ++ni) {
            float* a = acc[mi][ni];
            const int r = rA + mi * 16;
            const int cg = cA + ni * 8;
            if (cg < 768) {
                const int which = cg >> 8, rem = cg & 255, h = rem >> 3, d = rem & 7;
                float* dst = (which == 0) ? g_pq : (which == 1) ? g_pk : g_pv;
                const float scl = (which == 0) ? 2.0f : 1.0f;
                *(float2*)&dst[((size_t)h * S_LEN + r) * NB + d] =
                    make_float2(scl * fsigmoid(a[0]), scl * fsigmoid(a[1]));
                *(float2*)&dst[((size_t)h * S_LEN + r + 8) * NB + d] =
                    make_float2(scl * fsigmoid(a[2]), scl * fsigmoid(a[3]));
            } else {
                const int col = cg - 768;
                *(float2*)&out[(size_t)r * D_DIM + col] = make_float2(a[0], a[1]);
                *(float2*)&out[(size_t)(r + 8) * D_DIM + col] = make_float2(a[2], a[3]);
            }
        }
    }
}

// ---------------- fp32 GEMM tile core (PROVEN in R3) ----------------
__device__ __forceinline__ void gemm_tile_128x64(
    const float* __restrict__ A, const float* __restrict__ B,
    int K, int N, int brow, int bcol, float (&acc)[8][4])
{
    __shared__ __align__(16) float As[16][132];
    __shared__ __align__(16) float Bs[16][64];
    const int tid = threadIdx.x;
    const int tx = tid & 15;
    const int ty = tid >> 4;

    const int ar = tid >> 2;
    const int ac = (tid & 3) * 4;
    const int br = tid >> 4;
    const int bc = (tid & 15) * 4;

#pragma unroll
    for (int i = 0; i < 8; ++i)
#pragma unroll
        for (int j = 0; j < 4; ++j) acc[i][j] = 0.0f;

    for (int k0 = 0; k0 < K; k0 += 16) {
        float4 a0 = *(const float4*)&A[(size_t)(brow + ar) * K + k0 + ac];
        float4 a1 = *(const float4*)&A[(size_t)(brow + ar + 64) * K + k0 + ac];
        float4 bv = *(const float4*)&B[(size_t)(k0 + br) * N + bcol + bc];
        As[ac + 0][ar] = a0.x; As[ac + 1][ar] = a0.y;
        As[ac + 2][ar] = a0.z; As[ac + 3][ar] = a0.w;
        As[ac + 0][ar + 64] = a1.x; As[ac + 1][ar + 64] = a1.y;
        As[ac + 2][ar + 64] = a1.z; As[ac + 3][ar + 64] = a1.w;
        *(float4*)&Bs[br][bc] = bv;
        __syncthreads();
#pragma unroll
        for (int k = 0; k < 16; ++k) {
            float4 x0 = *(const float4*)&As[k][ty * 8];
            float4 x1 = *(const float4*)&As[k][ty * 8 + 4];
            float4 y0 = *(const float4*)&Bs[k][tx * 4];
            float a[8] = {x0.x, x0.y, x0.z, x0.w, x1.x, x1.y, x1.z, x1.w};
            float b[4] = {y0.x, y0.y, y0.z, y0.w};
#pragma unroll
            for (int i = 0; i < 8; ++i)
#pragma unroll
                for (int j = 0; j < 4; ++j)
                    acc[i][j] = fmaf(a[i], b[j], acc[i][j]);
        }
        __syncthreads();
    }
}

// ---------------- small kernels ----------------
__global__ void sumk_kernel() {
    int idx = blockIdx.x * blockDim.x + threadIdx.x;
    if (idx < NH * S_LEN) {
        const float* p = &g_pk[(size_t)idx * NB];
        float s = 0.f;
#pragma unroll
        for (int d = 0; d < NB; ++d) s += p[d];
        g_sumk[idx] = s;
    }
}

__global__ void bias_kernel(const float* __restrict__ e0, const float* __restrict__ Wo) {
    int n = blockIdx.x * blockDim.x + threadIdx.x;
    if (n < D_DIM) {
        float s = 0.f;
        for (int j = 0; j < HB; ++j) s = fmaf(e0[j], Wo[(size_t)j * D_DIM + n], s);
        g_bias[n] = s;
    }
}

// ---------------- causal attention (fp32, PROVEN) ----------------
__global__ void __launch_bounds__(128) attn_kernel(
    const float* __restrict__ e0, const float* __restrict__ e1)
{
    const int h = blockIdx.y;
    const int qt = blockIdx.x;
    const int tid = threadIdx.x;
    const int q = qt * 128 + tid;

    __shared__ __align__(16) float sk[128 * 8];
    __shared__ __align__(16) float sv[128 * 8];
    __shared__ float ssum[128];

    float pq[8];
    {
        const float4* p = (const float4*)&g_pq[((size_t)h * S_LEN + q) * NB];
        float4 p0 = p[0], p1 = p[1];
        pq[0] = p0.x; pq[1] = p0.y; pq[2] = p0.z; pq[3] = p0.w;
        pq[4] = p1.x; pq[5] = p1.y; pq[6] = p1.z; pq[7] = p1.w;
    }
    float acc[8] = {0, 0, 0, 0, 0, 0, 0, 0};
    float l = 0.f;

    const float* kbase = &g_pk[(size_t)h * S_LEN * NB];
    const float* vbase = &g_pv[(size_t)h * S_LEN * NB];

    for (int kt = 0; kt <= qt; ++kt) {
        const float4* kp = (const float4*)(kbase + (size_t)kt * 128 * NB);
        const float4* vp = (const float4*)(vbase + (size_t)kt * 128 * NB);
        ((float4*)sk)[tid]       = kp[tid];
        ((float4*)sk)[tid + 128] = kp[tid + 128];
        ((float4*)sv)[tid]       = vp[tid];
        ((float4*)sv)[tid + 128] = vp[tid + 128];
        ssum[tid] = g_sumk[h * S_LEN + kt * 128 + tid];
        __syncthreads();

        const int kmax = (kt == qt) ? (tid + 1) : 128;
        const float4* sk4 = (const float4*)sk;
        const float4* sv4 = (const float4*)sv;
        for (int kk = 0; kk < kmax; ++kk) {
            float4 k0 = sk4[kk * 2];
            float4 k1 = sk4[kk * 2 + 1];
            float dot = -ssum[kk];
            dot = fmaf(pq[0], k0.x, dot); dot = fmaf(pq[1], k0.y, dot);
            dot = fmaf(pq[2], k0.z, dot); dot = fmaf(pq[3], k0.w, dot);
            dot = fmaf(pq[4], k1.x, dot); dot = fmaf(pq[5], k1.y, dot);
            dot = fmaf(pq[6], k1.z, dot); dot = fmaf(pq[7], k1.w, dot);
            float e = __expf(dot);
            l += e;
            float4 v0 = sv4[kk * 2];
            float4 v1 = sv4[kk * 2 + 1];
            acc[0] = fmaf(e, v0.x, acc[0]); acc[1] = fmaf(e, v0.y, acc[1]);
            acc[2] = fmaf(e, v0.z, acc[2]); acc[3] = fmaf(e, v0.w, acc[3]);
            acc[4] = fmaf(e, v1.x, acc[4]); acc[5] = fmaf(e, v1.y, acc[5]);
            acc[6] = fmaf(e, v1.z, acc[6]); acc[7] = fmaf(e, v1.w, acc[7]);
        }
        __syncthreads();
    }

    float inv = 1.0f / l;
    float o[8];
#pragma unroll
    for (int d = 0; d < 8; ++d) {
        int j = h * 8 + d;
        o[d] = acc[d] * inv * (e1[j] - e0[j]);
    }
    float4* outp = (float4*)&g_op[(size_t)q * HB + h * 8];
    outp[0] = make_float4(o[0], o[1], o[2], o[3]);
    outp[1] = make_float4(o[4], o[5], o[6], o[7]);
}

// final (fp32, PROVEN): out = (g_op @ Wo + bias) * sigmoid(gate_pre)
__global__ void __launch_bounds__(256) final_kernel(
    const float* __restrict__ Wo, float* __restrict__ out)
{
    int brow = blockIdx.y * 128, bcol = blockIdx.x * 64;
    float acc[8][4];
    gemm_tile_128x64(g_op, Wo, HB, D_DIM, brow, bcol, acc);
    int tx = threadIdx.x & 15, ty = threadIdx.x >> 4;
    int c0 = bcol + tx * 4;
    float b0 = g_bias[c0], b1 = g_bias[c0 + 1], b2 = g_bias[c0 + 2], b3 = g_bias[c0 + 3];
#pragma unroll
    for (int i = 0; i < 8; ++i) {
        int r = brow + ty * 8 + i;
        size_t base = (size_t)r * D_DIM + c0;
        float4 g = *(float4*)&out[base];
        float4 v;
        v.x = (acc[i][0] + b0) * fsigmoid(g.x);
        v.y = (acc[i][1] + b1) * fsigmoid(g.y);
        v.z = (acc[i][2] + b2) * fsigmoid(g.z);
        v.w = (acc[i][3] + b3) * fsigmoid(g.w);
        *(float4*)&out[base] = v;
    }
}

// ---------------- launch ----------------
extern "C" void kernel_launch(void* const* d_in, const int* in_sizes, int n_in,
                              void* d_out, int out_size)
{
    (void)in_sizes; (void)n_in; (void)out_size;
    const float* hs = (const float*)d_in[0];
    const float* Wq = (const float*)d_in[1];
    const float* Wk = (const float*)d_in[2];
    const float* Wv = (const float*)d_in[3];
    const float* Wo = (const float*)d_in[4];
    const float* Wg = (const float*)d_in[5];
    const float* e0 = (const float*)d_in[6];
    const float* e1 = (const float*)d_in[7];
    float* out = (float*)d_out;

    dim3 tb(32, 8);
    pack_hilo<<<(S_LEN * D_DIM / 4 + 255) / 256, 256>>>(hs, g_hsH, g_hsL, S_LEN * D_DIM / 4);
    pack_T<<<dim3(HB / 32, D_DIM / 32), tb>>>(Wq, g_WbigH, g_WbigL, D_DIM, HB, 0, D_DIM);
    pack_T<<<dim3(HB / 32, D_DIM / 32), tb>>>(Wk, g_WbigH, g_WbigL, D_DIM, HB, 256, D_DIM);
    pack_T<<<dim3(HB / 32, D_DIM / 32), tb>>>(Wv, g_WbigH, g_WbigL, D_DIM, HB, 512, D_DIM);
    pack_T<<<dim3(D_DIM / 32, D_DIM / 32), tb>>>(Wg, g_WbigH, g_WbigL, D_DIM, D_DIM, 768, D_DIM);
    bias_kernel<<<(D_DIM + 255) / 256, 256>>>(e0, Wo);

    // fused qkv+gate GEMM (tensor cores; writes g_pq/g_pk/g_pv + gate preact -> out)
    fused_qkvgate<<<dim3(NBIG / BN, S_LEN / BM), 256, GEMM_SMEM>>>(
        g_hsH, g_hsL, g_WbigH, g_WbigL, out);

    sumk_kernel<<<(NH * S_LEN + 255) / 256, 256>>>();
    attn_kernel<<<dim3(S_LEN / 128, NH), 128>>>(e0, e1);

    // final (fp32, PROVEN): out = (op @ Wo + bias) * sigmoid(out)
    final_kernel<<<dim3(D_DIM / 64, S_LEN / 128), 256>>>(Wo, out);
}

// round 12
// speedup vs baseline: 14.0342x; 14.0342x over previous
#include <cuda_runtime.h>
#include <cstdint>

#define S_LEN 2048
#define D_DIM 2048
#define NH 32
#define NB 8
#define HB 256    // NH*NB
#define NBIG 2816 // 768 qkv + 2048 gate

// -------- scratch (no allocations allowed) --------
__device__ float g_pq[NH * S_LEN * NB];   // [h][s][bit], pre-scaled by 2
__device__ float g_pk[NH * S_LEN * NB];
__device__ float g_pv[NH * S_LEN * NB];
__device__ float g_sumk[NH * S_LEN];
__device__ float g_op[S_LEN * HB];        // (e1-e0)*attn_out
__device__ float g_bias[D_DIM];           // e0 @ Wo

__device__ __forceinline__ float fsigmoid(float x) {
    return 1.0f / (1.0f + __expf(-x));
}
__device__ __forceinline__ uint32_t smem_u32(const void* p) {
    uint32_t a;
    asm("{ .reg .u64 t; cvta.to.shared.u64 t, %1; cvt.u32.u64 %0, t; }" : "=r"(a) : "l"(p));
    return a;
}
__device__ __forceinline__ void cp16(uint32_t dst, const void* src) {
    asm volatile("cp.async.cg.shared.global [%0], [%1], 16;" :: "r"(dst), "l"(src));
}
__device__ __forceinline__ void cp_commit() {
    asm volatile("cp.async.commit_group;" ::: "memory");
}
template <int N> __device__ __forceinline__ void cp_wait() {
    asm volatile("cp.async.wait_group %0;" :: "n"(N) : "memory");
}
// packed fp32x2 FMA: d = a*b + d (per 32-bit lane)
__device__ __forceinline__ void fma2(float2& d, float2 a, float2 b) {
    asm("fma.rn.f32x2 %0, %1, %2, %0;"
        : "+l"(reinterpret_cast<unsigned long long&>(d))
        : "l"(reinterpret_cast<unsigned long long&>(a)),
          "l"(reinterpret_cast<unsigned long long&>(b)));
}
__device__ __forceinline__ float2 dup2(float a) {
    float2 r;
    asm("mov.b64 %0, {%1, %1};"
        : "=l"(reinterpret_cast<unsigned long long&>(r)) : "f"(a));
    return r;
}

// ---------------- f32x2 GEMM core ----------------
// C[128,128] tile of A[M,K] x B[K,N] (both row-major). 256 threads, 8x8/thread.
#define GBK 16
#define AROW 20                 // A smem row stride in floats (16 data + 4 pad)
#define ASZ (128 * AROW)        // 2560 floats
#define BSZ (GBK * 128)         // 2048 floats

__device__ __forceinline__ void g_load_chunk(
    const float* __restrict__ A, const float* __restrict__ B,
    int K, int Nst, int arow0, int bcol, int k0,
    float* as, float* bs, int tid)
{
#pragma unroll
    for (int i = 0; i < 2; ++i) {     // A tile: 128 rows x 16 floats
        int idx = tid + i * 256;
        int r = idx >> 2, q = idx & 3;
        cp16(smem_u32(as + r * AROW + q * 4),
             A + (size_t)(arow0 + r) * K + k0 + q * 4);
    }
#pragma unroll
    for (int i = 0; i < 2; ++i) {     // B tile: 16 rows x 128 floats
        int idx = tid + i * 256;
        int kr = idx >> 5, nq = idx & 31;
        cp16(smem_u32(bs + kr * 128 + nq * 4),
             B + (size_t)(k0 + kr) * Nst + bcol + nq * 4);
    }
}

__device__ __forceinline__ void g_compute_chunk(
    const float* __restrict__ as, const float* __restrict__ bs,
    int m0, int n0, float2 (&acc)[8][4])
{
#pragma unroll
    for (int k = 0; k < GBK; ++k) {
        float a[8];
#pragma unroll
        for (int mi = 0; mi < 8; ++mi) a[mi] = as[(m0 + mi) * AROW + k];
        float4 b0 = *(const float4*)&bs[k * 128 + n0];
        float4 b1 = *(const float4*)&bs[k * 128 + n0 + 4];
        float2 b2[4] = {{b0.x, b0.y}, {b0.z, b0.w}, {b1.x, b1.y}, {b1.z, b1.w}};
#pragma unroll
        for (int mi = 0; mi < 8; ++mi) {
            float2 am = dup2(a[mi]);
#pragma unroll
            for (int n2 = 0; n2 < 4; ++n2) fma2(acc[mi][n2], am, b2[n2]);
        }
    }
}

// ---------------- fused qkv + gate GEMM ----------------
// grid (22, 16): x<6 -> qkv tiles (Wq/Wk/Wv, N=256, 2 tiles each); x>=6 -> gate (Wg).
__global__ void __launch_bounds__(256) fused_qkvgate(
    const float* __restrict__ hs, const float* __restrict__ Wq,
    const float* __restrict__ Wk, const float* __restrict__ Wv,
    const float* __restrict__ Wg, float* __restrict__ out)
{
    __shared__ __align__(16) float As[2][ASZ];
    __shared__ __align__(16) float Bs[2][BSZ];

    const int tid = threadIdx.x;
    const int xt = blockIdx.x;
    const int brow = blockIdx.y * 128;

    const float* Bsrc;
    int bcol, Nst, mat = -1;
    if (xt < 6) {
        mat = xt >> 1;
        Bsrc = (mat == 0) ? Wq : (mat == 1) ? Wk : Wv;
        bcol = (xt & 1) * 128;
        Nst = HB;
    } else {
        Bsrc = Wg;
        bcol = (xt - 6) * 128;
        Nst = D_DIM;
    }

    float2 acc[8][4];
#pragma unroll
    for (int mi = 0; mi < 8; ++mi)
#pragma unroll
        for (int n2 = 0; n2 < 4; ++n2) acc[mi][n2] = make_float2(0.f, 0.f);

    const int m0 = (tid >> 4) * 8, n0 = (tid & 15) * 8;
    const int nch = D_DIM / GBK;  // 128

    g_load_chunk(hs, Bsrc, D_DIM, Nst, brow, bcol, 0, As[0], Bs[0], tid);
    cp_commit();
    for (int c = 0; c < nch; ++c) {
        if (c + 1 < nch)
            g_load_chunk(hs, Bsrc, D_DIM, Nst, brow, bcol, (c + 1) * GBK,
                         As[(c + 1) & 1], Bs[(c + 1) & 1], tid);
        cp_commit();
        cp_wait<1>();
        __syncthreads();
        g_compute_chunk(As[c & 1], Bs[c & 1], m0, n0, acc);
        __syncthreads();
    }

    if (mat >= 0) {
        float* dst = (mat == 0) ? g_pq : (mat == 1) ? g_pk : g_pv;
        const float scl = (mat == 0) ? 2.0f : 1.0f;
#pragma unroll
        for (int mi = 0; mi < 8; ++mi) {
            int s = brow + m0 + mi;
#pragma unroll
            for (int n2 = 0; n2 < 4; ++n2) {
                int c = bcol + n0 + 2 * n2;
                int h = c >> 3, d = c & 7;
                float2 v = acc[mi][n2];
                v.x = scl * fsigmoid(v.x);
                v.y = scl * fsigmoid(v.y);
                *(float2*)&dst[((size_t)h * S_LEN + s) * NB + d] = v;
            }
        }
    } else {
#pragma unroll
        for (int mi = 0; mi < 8; ++mi) {
            int r = brow + m0 + mi;
            size_t base = (size_t)r * D_DIM + bcol + n0;
            *(float4*)&out[base] =
                make_float4(acc[mi][0].x, acc[mi][0].y, acc[mi][1].x, acc[mi][1].y);
            *(float4*)&out[base + 4] =
                make_float4(acc[mi][2].x, acc[mi][2].y, acc[mi][3].x, acc[mi][3].y);
        }
    }
}

// ---------------- final GEMM: out = (g_op @ Wo + bias) * sigmoid(out) ----------------
__global__ void __launch_bounds__(256) final_gemm(
    const float* __restrict__ Wo, float* __restrict__ out)
{
    __shared__ __align__(16) float As[2][ASZ];
    __shared__ __align__(16) float Bs[2][BSZ];

    const int tid = threadIdx.x;
    const int brow = blockIdx.y * 128;
    const int bcol = blockIdx.x * 128;

    float2 acc[8][4];
#pragma unroll
    for (int mi = 0; mi < 8; ++mi)
#pragma unroll
        for (int n2 = 0; n2 < 4; ++n2) acc[mi][n2] = make_float2(0.f, 0.f);

    const int m0 = (tid >> 4) * 8, n0 = (tid & 15) * 8;
    const int nch = HB / GBK;  // 16

    g_load_chunk(g_op, Wo, HB, D_DIM, brow, bcol, 0, As[0], Bs[0], tid);
    cp_commit();
    for (int c = 0; c < nch; ++c) {
        if (c + 1 < nch)
            g_load_chunk(g_op, Wo, HB, D_DIM, brow, bcol, (c + 1) * GBK,
                         As[(c + 1) & 1], Bs[(c + 1) & 1], tid);
        cp_commit();
        cp_wait<1>();
        __syncthreads();
        g_compute_chunk(As[c & 1], Bs[c & 1], m0, n0, acc);
        __syncthreads();
    }

#pragma unroll
    for (int mi = 0; mi < 8; ++mi) {
        int r = brow + m0 + mi;
        int c0 = bcol + n0;
        size_t base = (size_t)r * D_DIM + c0;
#pragma unroll
        for (int n2 = 0; n2 < 4; ++n2) {
            float2 b = *(float2*)&g_bias[c0 + 2 * n2];
            float2 g = *(float2*)&out[base + 2 * n2];
            float2 v;
            v.x = (acc[mi][n2].x + b.x) * fsigmoid(g.x);
            v.y = (acc[mi][n2].y + b.y) * fsigmoid(g.y);
            *(float2*)&out[base + 2 * n2] = v;
        }
    }
}

// ---------------- small kernels (PROVEN) ----------------
__global__ void sumk_kernel() {
    int idx = blockIdx.x * blockDim.x + threadIdx.x;
    if (idx < NH * S_LEN) {
        const float* p = &g_pk[(size_t)idx * NB];
        float s = 0.f;
#pragma unroll
        for (int d = 0; d < NB; ++d) s += p[d];
        g_sumk[idx] = s;
    }
}

__global__ void bias_kernel(const float* __restrict__ e0, const float* __restrict__ Wo) {
    int n = blockIdx.x * blockDim.x + threadIdx.x;
    if (n < D_DIM) {
        float s = 0.f;
        for (int j = 0; j < HB; ++j) s = fmaf(e0[j], Wo[(size_t)j * D_DIM + n], s);
        g_bias[n] = s;
    }
}

// ---------------- causal attention (fp32, PROVEN) ----------------
__global__ void __launch_bounds__(128) attn_kernel(
    const float* __restrict__ e0, const float* __restrict__ e1)
{
    const int h = blockIdx.y;
    const int qt = blockIdx.x;
    const int tid = threadIdx.x;
    const int q = qt * 128 + tid;

    __shared__ __align__(16) float sk[128 * 8];
    __shared__ __align__(16) float sv[128 * 8];
    __shared__ float ssum[128];

    float pq[8];
    {
        const float4* p = (const float4*)&g_pq[((size_t)h * S_LEN + q) * NB];
        float4 p0 = p[0], p1 = p[1];
        pq[0] = p0.x; pq[1] = p0.y; pq[2] = p0.z; pq[3] = p0.w;
        pq[4] = p1.x; pq[5] = p1.y; pq[6] = p1.z; pq[7] = p1.w;
    }
    float acc[8] = {0, 0, 0, 0, 0, 0, 0, 0};
    float l = 0.f;

    const float* kbase = &g_pk[(size_t)h * S_LEN * NB];
    const float* vbase = &g_pv[(size_t)h * S_LEN * NB];

    for (int kt = 0; kt <= qt; ++kt) {
        const float4* kp = (const float4*)(kbase + (size_t)kt * 128 * NB);
        const float4* vp = (const float4*)(vbase + (size_t)kt * 128 * NB);
        ((float4*)sk)[tid]       = kp[tid];
        ((float4*)sk)[tid + 128] = kp[tid + 128];
        ((float4*)sv)[tid]       = vp[tid];
        ((float4*)sv)[tid + 128] = vp[tid + 128];
        ssum[tid] = g_sumk[h * S_LEN + kt * 128 + tid];
        __syncthreads();

        const int kmax = (kt == qt) ? (tid + 1) : 128;
        const float4* sk4 = (const float4*)sk;
        const float4* sv4 = (const float4*)sv;
        for (int kk = 0; kk < kmax; ++kk) {
            float4 k0 = sk4[kk * 2];
            float4 k1 = sk4[kk * 2 + 1];
            float dot = -ssum[kk];
            dot = fmaf(pq[0], k0.x, dot); dot = fmaf(pq[1], k0.y, dot);
            dot = fmaf(pq[2], k0.z, dot); dot = fmaf(pq[3], k0.w, dot);
            dot = fmaf(pq[4], k1.x, dot); dot = fmaf(pq[5], k1.y, dot);
            dot = fmaf(pq[6], k1.z, dot); dot = fmaf(pq[7], k1.w, dot);
            float e = __expf(dot);
            l += e;
            float4 v0 = sv4[kk * 2];
            float4 v1 = sv4[kk * 2 + 1];
            acc[0] = fmaf(e, v0.x, acc[0]); acc[1] = fmaf(e, v0.y, acc[1]);
            acc[2] = fmaf(e, v0.z, acc[2]); acc[3] = fmaf(e, v0.w, acc[3]);
            acc[4] = fmaf(e, v1.x, acc[4]); acc[5] = fmaf(e, v1.y, acc[5]);
            acc[6] = fmaf(e, v1.z, acc[6]); acc[7] = fmaf(e, v1.w, acc[7]);
        }
        __syncthreads();
    }

    float inv = 1.0f / l;
    float o[8];
#pragma unroll
    for (int d = 0; d < 8; ++d) {
        int j = h * 8 + d;
        o[d] = acc[d] * inv * (e1[j] - e0[j]);
    }
    float4* outp = (float4*)&g_op[(size_t)q * HB + h * 8];
    outp[0] = make_float4(o[0], o[1], o[2], o[3]);
    outp[1] = make_float4(o[4], o[5], o[6], o[7]);
}

// ---------------- launch ----------------
extern "C" void kernel_launch(void* const* d_in, const int* in_sizes, int n_in,
                              void* d_out, int out_size)
{
    (void)in_sizes; (void)n_in; (void)out_size;
    const float* hs = (const float*)d_in[0];
    const float* Wq = (const float*)d_in[1];
    const float* Wk = (const float*)d_in[2];
    const float* Wv = (const float*)d_in[3];
    const float* Wo = (const float*)d_in[4];
    const float* Wg = (const float*)d_in[5];
    const float* e0 = (const float*)d_in[6];
    const float* e1 = (const float*)d_in[7];
    float* out = (float*)d_out;

    bias_kernel<<<(D_DIM + 255) / 256, 256>>>(e0, Wo);

    // fused qkv + gate (f32x2): writes g_pq/g_pk/g_pv + gate preact -> out
    fused_qkvgate<<<dim3(NBIG / 128, S_LEN / 128), 256>>>(hs, Wq, Wk, Wv, Wg, out);

    sumk_kernel<<<(NH * S_LEN + 255) / 256, 256>>>();
    attn_kernel<<<dim3(S_LEN / 128, NH), 128>>>(e0, e1);

    // final (f32x2): out = (g_op @ Wo + bias) * sigmoid(out)
    final_gemm<<<dim3(D_DIM / 128, S_LEN / 128), 256>>>(Wo, out);
}